// round 9
// baseline (speedup 1.0000x reference)
#include <cuda_runtime.h>
#include <cuda_fp16.h>
#include <math.h>
#include <stdint.h>

#define NLV   16
#define TBITS 19
#define TSZ   (1u << TBITS)
#define BLOCK 256
#define PD_CAP 393216   // capacity of dense pair-table (entries), actual ~330940

typedef unsigned int u32;

struct LvlParams {
    float scale[NLV];
    int   res[NLV];
    int   dense[NLV];
    int   pdoff[NLV];   // entry offset into g_pd for dense levels
};

struct BuildParams {
    int lvl[8];
    int res[8];
    int off[8];
    int nd;
    int total;
};

// dense pair-table: entry j of level l at pdoff[l]+j holds (T[j], T[j+1 along x, clamped])
__device__ __align__(16) float4 g_pd[PD_CAP];

// softplus(10z)/10 = max(z,0) + (ln2/10)*lg2(1 + 2^(-10*log2e*|z|))
__device__ __forceinline__ float softplus10(float z) {
    float e, l;
    float a = -14.426950408889634f * fabsf(z);
    asm("ex2.approx.ftz.f32 %0, %1;" : "=f"(e) : "f"(a));
    float p = 1.0f + e;
    asm("lg2.approx.ftz.f32 %0, %1;" : "=f"(l) : "f"(p));
    return fmaf(l, 0.069314718055994531f, fmaxf(z, 0.0f));
}

// pack two f32 -> f16x2; first operand lands in HIGH half
__device__ __forceinline__ u32 f22h2(float hi, float lo) {
    u32 r;
    asm("cvt.rn.f16x2.f32 %0, %1, %2;" : "=r"(r) : "f"(hi), "f"(lo));
    return r;
}

__device__ __forceinline__ void ldsm4(u32& r0, u32& r1, u32& r2, u32& r3, u32 addr) {
    asm volatile("ldmatrix.sync.aligned.m8n8.x4.shared.b16 {%0,%1,%2,%3}, [%4];"
        : "=r"(r0), "=r"(r1), "=r"(r2), "=r"(r3) : "r"(addr));
}

__device__ __forceinline__ void mma16816(float* d, const u32* a, u32 b0, u32 b1) {
    asm volatile("mma.sync.aligned.m16n8k16.row.col.f32.f16.f16.f32 "
        "{%0,%1,%2,%3},{%4,%5,%6,%7},{%8,%9},{%0,%1,%2,%3};"
        : "+f"(d[0]), "+f"(d[1]), "+f"(d[2]), "+f"(d[3])
        : "r"(a[0]), "r"(a[1]), "r"(a[2]), "r"(a[3]), "r"(b0), "r"(b1));
}

// =============== build kernel: dense pair-table ===============
__global__ void build_pd(const float* __restrict__ table, BuildParams B)
{
    int f = blockIdx.x * blockDim.x + threadIdx.x;
    if (f >= B.total) return;
    int l = 0, res = 1, j = f;
    #pragma unroll
    for (int d = 0; d < 8; d++) {
        if (d < B.nd && f >= B.off[d]) { l = B.lvl[d]; res = B.res[d]; j = f - B.off[d]; }
    }
    const float2* t2 = reinterpret_cast<const float2*>(table) + (size_t)l * TSZ;
    int qx = j % res;
    float2 c0 = __ldg(&t2[j]);
    float2 c1 = __ldg(&t2[(qx < res - 1) ? j + 1 : j]);
    g_pd[f] = make_float4(c0.x, c0.y, c1.x, c1.y);
}

// =============== per-(point,level) encode -> f16x2 feature ===============
__device__ __forceinline__ u32 enc_slot(float px, float py, float pz, int l,
                                        const LvlParams& P,
                                        const float* __restrict__ table)
{
    const float sc  = P.scale[l];
    const int   res = P.res[l];

    float fx = px * sc + 0.5f, fy = py * sc + 0.5f, fz = pz * sc + 0.5f;
    float gx = floorf(fx), gy = floorf(fy), gz = floorf(fz);
    float wx = fx - gx, wy = fy - gy, wz = fz - gz;
    int cx = (int)gx, cy = (int)gy, cz = (int)gz;
    const float wx0 = 1.f - wx, wy0 = 1.f - wy, wz0 = 1.f - wz;

    float f0 = 0.f, f1 = 0.f;

    if (P.dense[l]) {
        // all 8 corners via 4 pair-loads from g_pd, zero fallbacks
        int jx  = min(max(cx, 0), res - 1);
        int ty0 = min(max(cy,     0), res - 1) * res;
        int ty1 = min(max(cy + 1, 0), res - 1) * res;
        int tz0 = min(max(cz,     0), res - 1) * (res * res);
        int tz1 = min(max(cz + 1, 0), res - 1) * (res * res);
        int base = P.pdoff[l] + jx;

        float4 q[4];
        q[0] = __ldg(&g_pd[base + ty0 + tz0]);
        q[1] = __ldg(&g_pd[base + ty0 + tz1]);
        q[2] = __ldg(&g_pd[base + ty1 + tz0]);
        q[3] = __ldg(&g_pd[base + ty1 + tz1]);

        #pragma unroll
        for (int p = 0; p < 4; p++) {
            const int oy = (p >> 1) & 1, oz = p & 1;
            float wyz = (oy ? wy : wy0) * (oz ? wz : wz0);
            float w0 = wx0 * wyz, w1 = wx * wyz;
            f0 = fmaf(w0, q[p].x, fmaf(w1, q[p].z, f0));
            f1 = fmaf(w0, q[p].y, fmaf(w1, q[p].w, f1));
        }
    } else {
        const float2* t2 = reinterpret_cast<const float2*>(table) + (size_t)l * TSZ;
        const float4* t4 = reinterpret_cast<const float4*>(t2);
        u32 ux = (u32)cx, uy = (u32)cy, uz = (u32)cz;
        u32 ty0 = uy * 2654435761u, ty1 = ty0 + 2654435761u;
        u32 tz0 = uz * 805459861u,  tz1 = tz0 + 805459861u;

        u32 i0[4], i1[4];
        #pragma unroll
        for (int p = 0; p < 4; p++) {
            const int oy = (p >> 1) & 1, oz = p & 1;
            u32 s = (oy ? ty1 : ty0) ^ (oz ? tz1 : tz0);
            i0[p] = (ux ^ s) & (TSZ - 1u);
            i1[p] = ((ux + 1u) ^ s) & (TSZ - 1u);
        }

        float4 q[4];
        #pragma unroll
        for (int p = 0; p < 4; p++) q[p] = __ldg(&t4[i0[p] >> 1]);

        float2 e[4];
        #pragma unroll
        for (int p = 0; p < 4; p++) {
            e[p] = make_float2(0.f, 0.f);
            if ((i0[p] ^ i1[p]) != 1u) e[p] = __ldg(&t2[i1[p]]);
        }

        #pragma unroll
        for (int p = 0; p < 4; p++) {
            const int oy = (p >> 1) & 1, oz = p & 1;
            const bool hi = (i0[p] & 1u) != 0u;
            float2 c0 = hi ? make_float2(q[p].z, q[p].w) : make_float2(q[p].x, q[p].y);
            float2 ot = hi ? make_float2(q[p].x, q[p].y) : make_float2(q[p].z, q[p].w);
            float2 c1 = ((i0[p] ^ i1[p]) == 1u) ? ot : e[p];
            float wyz = (oy ? wy : wy0) * (oz ? wz : wz0);
            float w0 = wx0 * wyz, w1 = wx * wyz;
            f0 = fmaf(w0, c0.x, fmaf(w1, c1.x, f0));
            f1 = fmaf(w0, c0.y, fmaf(w1, c1.y, f1));
        }
    }
    return f22h2(f1, f0);
}

__global__ void __launch_bounds__(BLOCK, 3)
sdf_kernel(const float* __restrict__ x,
           const float* __restrict__ table,
           const float* __restrict__ w1,
           const float* __restrict__ w2,
           const float* __restrict__ w3,
           const float* __restrict__ w4,
           float* __restrict__ out,
           int n, LvlParams P)
{
    __shared__ __align__(16) __half s_w1[64 * 40];
    __shared__ __align__(16) __half s_w2[64 * 72];
    __shared__ __align__(16) __half s_w3[64 * 72];
    __shared__ float s_w4[64];
    __shared__ float s_x[BLOCK * 3];

    const int tid  = threadIdx.x;
    const int lane = tid & 31;
    const int warp = tid >> 5;
    const int g    = lane >> 2;
    const int t    = lane & 3;

    // ---- prologue: weights -> fp16 smem; stage point coords ----
    for (int i = tid; i < 64 * 32; i += BLOCK) {
        int nn = i >> 5, kk = i & 31;
        s_w1[nn * 40 + kk] = __float2half_rn(w1[i]);
    }
    for (int i = tid; i < 64 * 64; i += BLOCK) {
        int nn = i >> 6, kk = i & 63;
        s_w2[nn * 72 + kk] = __float2half_rn(w2[i]);
        s_w3[nn * 72 + kk] = __float2half_rn(w3[i]);
    }
    if (tid < 64) s_w4[tid] = w4[tid];
    {
        int base = blockIdx.x * BLOCK * 3;
        #pragma unroll
        for (int it = 0; it < 3; it++) {
            int idx = it * BLOCK + tid;
            int gi = base + idx;
            s_x[idx] = (gi < n * 3) ? x[gi] : 0.f;
        }
    }
    __syncthreads();

    const u32 w1_b = (u32)__cvta_generic_to_shared(s_w1);
    const u32 w2_b = (u32)__cvta_generic_to_shared(s_w2);
    const u32 w3_b = (u32)__cvta_generic_to_shared(s_w3);

    #pragma unroll 1
    for (int mt = 0; mt < 2; mt++) {
        float d[8][4];
        u32   a[4][4];

        // ---- encode directly into A-fragment: lane owns pts {g, g+8}, levels {t,t+4,t+8,t+12} ----
        #pragma unroll 1
        for (int pt = 0; pt < 2; pt++) {
            int prow = warp * 32 + mt * 16 + g + 8 * pt;
            float px = s_x[prow * 3 + 0];
            float py = s_x[prow * 3 + 1];
            float pz = s_x[prow * 3 + 2];
            #pragma unroll 1
            for (int k = 0; k < 4; k++) {
                u32 v = enc_slot(px, py, pz, t + 4 * k, P, table);
                a[k >> 1][(k & 1) * 2 + pt] = v;
            }
        }

        // ---- layer 1: 32 -> 64 ----
        #pragma unroll
        for (int nt = 0; nt < 8; nt++)
            #pragma unroll
            for (int v = 0; v < 4; v++) d[nt][v] = 0.f;

        #pragma unroll
        for (int kt = 0; kt < 2; kt++)
            #pragma unroll
            for (int u = 0; u < 4; u++) {
                u32 b0, b1, b2, b3;
                u32 addr = w1_b + (u32)((u * 16 + (lane >> 4) * 8 + (lane & 7)) * 80
                                        + kt * 32 + ((lane >> 3) & 1) * 16);
                ldsm4(b0, b1, b2, b3, addr);
                mma16816(d[2 * u],     a[kt], b0, b1);
                mma16816(d[2 * u + 1], a[kt], b2, b3);
            }

        #pragma unroll
        for (int kk = 0; kk < 4; kk++) {
            a[kk][0] = f22h2(softplus10(d[2*kk][1]),   softplus10(d[2*kk][0]));
            a[kk][1] = f22h2(softplus10(d[2*kk][3]),   softplus10(d[2*kk][2]));
            a[kk][2] = f22h2(softplus10(d[2*kk+1][1]), softplus10(d[2*kk+1][0]));
            a[kk][3] = f22h2(softplus10(d[2*kk+1][3]), softplus10(d[2*kk+1][2]));
        }

        // ---- layers 2 and 3: 64 -> 64 ----
        #pragma unroll 1
        for (int layer = 0; layer < 2; layer++) {
            const u32 wb = (layer == 0) ? w2_b : w3_b;
            #pragma unroll
            for (int nt = 0; nt < 8; nt++)
                #pragma unroll
                for (int v = 0; v < 4; v++) d[nt][v] = 0.f;

            #pragma unroll
            for (int kt = 0; kt < 4; kt++)
                #pragma unroll
                for (int u = 0; u < 4; u++) {
                    u32 b0, b1, b2, b3;
                    u32 addr = wb + (u32)((u * 16 + (lane >> 4) * 8 + (lane & 7)) * 144
                                          + kt * 32 + ((lane >> 3) & 1) * 16);
                    ldsm4(b0, b1, b2, b3, addr);
                    mma16816(d[2 * u],     a[kt], b0, b1);
                    mma16816(d[2 * u + 1], a[kt], b2, b3);
                }

            if (layer == 0) {
                #pragma unroll
                for (int kk = 0; kk < 4; kk++) {
                    a[kk][0] = f22h2(softplus10(d[2*kk][1]),   softplus10(d[2*kk][0]));
                    a[kk][1] = f22h2(softplus10(d[2*kk][3]),   softplus10(d[2*kk][2]));
                    a[kk][2] = f22h2(softplus10(d[2*kk+1][1]), softplus10(d[2*kk+1][0]));
                    a[kk][3] = f22h2(softplus10(d[2*kk+1][3]), softplus10(d[2*kk+1][2]));
                }
            }
        }

        // ---- layer 4: 64 -> 1 ----
        {
            float p0 = 0.f, p1 = 0.f;
            #pragma unroll
            for (int nt = 0; nt < 8; nt++) {
                int c = nt * 8 + 2 * (lane & 3);
                float wv0 = s_w4[c], wv1 = s_w4[c + 1];
                p0 = fmaf(softplus10(d[nt][0]), wv0, p0);
                p0 = fmaf(softplus10(d[nt][1]), wv1, p0);
                p1 = fmaf(softplus10(d[nt][2]), wv0, p1);
                p1 = fmaf(softplus10(d[nt][3]), wv1, p1);
            }
            p0 += __shfl_xor_sync(0xffffffffu, p0, 1);
            p0 += __shfl_xor_sync(0xffffffffu, p0, 2);
            p1 += __shfl_xor_sync(0xffffffffu, p1, 1);
            p1 += __shfl_xor_sync(0xffffffffu, p1, 2);
            if ((lane & 3) == 0) {
                int r0 = blockIdx.x * BLOCK + warp * 32 + mt * 16 + (lane >> 2);
                if (r0 < n) out[r0] = p0;
                int r1 = r0 + 8;
                if (r1 < n) out[r1] = p1;
            }
        }
    }
}

extern "C" void kernel_launch(void* const* d_in, const int* in_sizes, int n_in,
                              void* d_out, int out_size)
{
    const float* x     = (const float*)d_in[0];
    const float* table = (const float*)d_in[1];
    const float* w1    = (const float*)d_in[2];
    const float* w2    = (const float*)d_in[3];
    const float* w3    = (const float*)d_in[4];
    const float* w4    = (const float*)d_in[5];
    float* out = (float*)d_out;

    const int n = in_sizes[0] / 3;

    LvlParams P;
    BuildParams B;
    B.nd = 0; B.total = 0;
    const double pls = exp2(7.0 / 15.0);
    const double l2s = log2(pls);
    for (int l = 0; l < NLV; l++) {
        double s = exp2((double)l * l2s) * 16.0 - 1.0;
        P.scale[l] = (float)s;
        long long r = (long long)ceil(s) + 1;
        P.res[l] = (int)r;
        bool dn = (r * r * r <= (long long)TSZ);
        P.dense[l] = dn ? 1 : 0;
        P.pdoff[l] = 0;
        if (dn && B.nd < 8) {
            long long cnt = r * r * r;
            if (B.total + cnt <= PD_CAP) {
                P.pdoff[l] = B.total;
                B.lvl[B.nd] = l;
                B.res[B.nd] = (int)r;
                B.off[B.nd] = B.total;
                B.nd++;
                B.total += (int)cnt;
            } else {
                P.dense[l] = 2;  // dense but no pd slot (shouldn't happen)
            }
        }
    }
    // safety: any level marked 2 falls back... (capacity is ample; mark as dense=1 path
    // requires pd, so ensure it never triggers)
    for (int l = 0; l < NLV; l++) if (P.dense[l] == 2) P.dense[l] = 0;  // unreachable for these params

    if (B.total > 0) {
        int bgrid = (B.total + 255) / 256;
        build_pd<<<bgrid, 256>>>(table, B);
    }

    int grid = (n + BLOCK - 1) / BLOCK;
    sdf_kernel<<<grid, BLOCK>>>(x, table, w1, w2, w3, w4, out, n, P);
}